// round 11
// baseline (speedup 1.0000x reference)
#include <cuda_runtime.h>

#define BATCH 8
#define HW    4096
#define CH    512
#define NMASK 1024
#define NCTX  3072
#define EPSF  1e-8f
#define NSPLIT 4

// ---------------- scratch ----------------------------------------------------
__device__ float g_Am[BATCH * CH * NMASK];            // [b][k][i]
__device__ float g_Bn[BATCH * CH * NCTX];             // [b][k][j]
__device__ float g_best[BATCH * NMASK * CH];
__device__ float g_mskn[BATCH * NMASK * CH];
__device__ float g_gen[BATCH * NMASK * CH];
__device__ float g_part[NSPLIT][BATCH * HW];
__device__ float g_invall[BATCH * HW];
__device__ float g_n2[BATCH * HW];
__device__ float g_invm[BATCH * NMASK];
__device__ float g_maxc[BATCH * NMASK];
__device__ float g_bn2[BATCH * NMASK];
__device__ unsigned long long g_packed[BATCH * NMASK];
__device__ int   g_imask[HW];

// ---------------- helpers ----------------------------------------------------
__device__ __forceinline__ void cp16(void* sdst, const void* gsrc) {
    unsigned saddr = (unsigned)__cvta_generic_to_shared(sdst);
    asm volatile("cp.async.ca.shared.global [%0], [%1], 16;\n" :: "r"(saddr), "l"(gsrc));
}
__device__ __forceinline__ unsigned ford(float f) {
    unsigned u = __float_as_uint(f);
    return (u & 0x80000000u) ? ~u : (u | 0x80000000u);
}
__device__ __forceinline__ float frcp(float x) {
    float r; asm("rcp.approx.f32 %0, %1;" : "=f"(r) : "f"(x)); return r;
}
__device__ __forceinline__ float frsq(float x) {
    float r; asm("rsqrt.approx.f32 %0, %1;" : "=f"(r) : "f"(x)); return r;
}
__device__ __forceinline__ void st_release_s32(volatile int* p, int v) {
    unsigned a = (unsigned)__cvta_generic_to_shared((void*)p);
    asm volatile("st.release.cta.shared.b32 [%0], %1;" :: "r"(a), "r"(v) : "memory");
}
__device__ __forceinline__ int ld_acquire_s32(volatile int* p) {
    unsigned a = (unsigned)__cvta_generic_to_shared((void*)p);
    int v;
    asm volatile("ld.acquire.cta.shared.b32 %0, [%1];" : "=r"(v) : "r"(a) : "memory");
    return v;
}

// ---------------- K A: gather A/B (also zeroes g_packed) --------------------
__global__ void k_gather(const float* __restrict__ x,
                         const int* __restrict__ np, const int* __restrict__ mp) {
    int k = blockIdx.x;
    int b = blockIdx.y;
    int t = threadIdx.x;        // 1024
    if (blockIdx.x == 0 && blockIdx.y == 0) {
#pragma unroll
        for (int i = t; i < BATCH * NMASK; i += 1024) g_packed[i] = 0ull;
    }
    const float* row = x + ((size_t)b * CH + k) * HW;
    g_Am[((size_t)b * CH + k) * NMASK + t] = row[mp[t]];
#pragma unroll
    for (int j = t; j < NCTX; j += 1024)
        g_Bn[((size_t)b * CH + k) * NCTX + j] = row[np[j]];
}

// ---------------- K B/C: column norms ----------------------------------------
__global__ void k_part(const float* __restrict__ x) {
    int p = blockIdx.x * 256 + threadIdx.x;
    int b = blockIdx.y;
    int z = blockIdx.z;
    const float* base = x + ((size_t)b * CH + (size_t)z * (CH / NSPLIT)) * HW + p;
    float s = 0.f;
#pragma unroll 8
    for (int c = 0; c < CH / NSPLIT; c++) {
        float v = base[(size_t)c * HW];
        s += v * v;
    }
    g_part[z][b * HW + p] = s;
}
__global__ void k_invall() {
    int i = blockIdx.x * 256 + threadIdx.x;
    float s = g_part[0][i] + g_part[1][i] + g_part[2][i] + g_part[3][i];
    g_n2[i] = s;
    g_invall[i] = 1.f / (sqrtf(s) + EPSF);
}

// ---------------- K D: fp32 GEMM (2-stage cp.async, f32x2 FFMA) -------------
#define BM 128
#define BN 128
#define BK 16
#define NT (CH / BK)

__global__ void __launch_bounds__(256, 2) k_gemm(const int* __restrict__ np) {
    __shared__ __align__(16) float As[2][BK][BM];
    __shared__ __align__(16) float Bs[2][BK][BN];

    int b  = blockIdx.z;
    int i0 = blockIdx.y * BM;
    int j0 = blockIdx.x * BN;
    int tid = threadIdx.x;
    int tx = tid & 15, ty = tid >> 4;
    int cA = tx * 4;

    const float* A  = g_Am + (size_t)b * CH * NMASK + i0;
    const float* Bp = g_Bn + (size_t)b * CH * NCTX  + j0;

    unsigned long long acc[8][4];
#pragma unroll
    for (int r = 0; r < 8; r++)
#pragma unroll
        for (int q = 0; q < 4; q++) acc[r][q] = 0ull;

#define COPY_TILE(t)                                                          \
    do {                                                                      \
        int s_ = (t) & 1;                                                     \
        const float* ga = A  + (size_t)((t) * BK + ty) * NMASK + cA;          \
        const float* gb = Bp + (size_t)((t) * BK + ty) * NCTX  + cA;          \
        cp16(&As[s_][ty][cA],      ga);                                       \
        cp16(&As[s_][ty][64 + cA], ga + 64);                                  \
        cp16(&Bs[s_][ty][cA],      gb);                                       \
        cp16(&Bs[s_][ty][64 + cA], gb + 64);                                  \
        asm volatile("cp.async.commit_group;\n");                             \
    } while (0)

    COPY_TILE(0);
    COPY_TILE(1);

#pragma unroll 1
    for (int t = 0; t < NT; t++) {
        if (t < NT - 1) asm volatile("cp.async.wait_group 1;\n");
        else            asm volatile("cp.async.wait_group 0;\n");
        __syncthreads();
        int s = t & 1;
#pragma unroll
        for (int kk = 0; kk < BK; kk++) {
            float4 a0 = *(const float4*)&As[s][kk][ty * 4];
            float4 a1 = *(const float4*)&As[s][kk][64 + ty * 4];
            ulonglong2 bv0 = *(const ulonglong2*)&Bs[s][kk][tx * 4];
            ulonglong2 bv1 = *(const ulonglong2*)&Bs[s][kk][64 + tx * 4];
            float ar[8] = {a0.x, a0.y, a0.z, a0.w, a1.x, a1.y, a1.z, a1.w};
            unsigned long long bq[4] = {bv0.x, bv0.y, bv1.x, bv1.y};
#pragma unroll
            for (int r = 0; r < 8; r++) {
                unsigned long long a2;
                asm("mov.b64 %0, {%1, %1};" : "=l"(a2) : "r"(__float_as_uint(ar[r])));
#pragma unroll
                for (int q = 0; q < 4; q++)
                    asm("fma.rn.f32x2 %0, %1, %2, %0;"
                        : "+l"(acc[r][q]) : "l"(a2), "l"(bq[q]));
            }
        }
        __syncthreads();
        if (t + 2 < NT) COPY_TILE(t + 2);
    }

    // epilogue: invc computed inline from g_invall + np
    float invc[8];
#pragma unroll
    for (int g = 0; g < 2; g++)
#pragma unroll
        for (int e = 0; e < 4; e++) {
            int jl = j0 + g * 64 + tx * 4 + e;
            invc[g * 4 + e] = g_invall[b * HW + np[jl]];
        }

#pragma unroll
    for (int r = 0; r < 8; r++) {
        int irow = (r < 4) ? (ty * 4 + r) : (64 + ty * 4 + (r - 4));
        unsigned long long bp = 0ull;
#pragma unroll
        for (int q = 0; q < 4; q++) {
            float lo = __uint_as_float((unsigned)acc[r][q]);
            float hi = __uint_as_float((unsigned)(acc[r][q] >> 32));
            float v0 = lo * invc[q * 2];
            float v1 = hi * invc[q * 2 + 1];
            int jg = j0 + ((q >> 1) * 64) + tx * 4 + (q & 1) * 2;
            unsigned long long p0 = ((unsigned long long)ford(v0) << 32) | (unsigned)(~(unsigned)jg);
            unsigned long long p1 = ((unsigned long long)ford(v1) << 32) | (unsigned)(~(unsigned)(jg + 1));
            if (p0 > bp) bp = p0;
            if (p1 > bp) bp = p1;
        }
#pragma unroll
        for (int o = 1; o < 16; o <<= 1) {
            unsigned long long other = __shfl_xor_sync(0xffffffffu, bp, o);
            if (other > bp) bp = other;
        }
        if (tx == 0) atomicMax(&g_packed[b * NMASK + i0 + irow], bp);
    }
}

// ---------------- K E: setup (imask + invm) ----------------------------------
__global__ void k_setup(const int* __restrict__ np, const int* __restrict__ mp) {
    int t = threadIdx.x;  // 1024, 1 block
    for (int p = t; p < HW; p += 1024) g_imask[p] = -1;
    __syncthreads();
    g_imask[mp[t]] = t;
    for (int i = t; i < BATCH * NMASK; i += 1024) {
        int b = i / NMASK;
        g_invm[i] = g_invall[b * HW + mp[i % NMASK]];
    }
}

// ---------------- K F: finalize pick + gather + |best|^2 --------------------
__global__ void k_finalize(const int* __restrict__ np) {
    int i = blockIdx.x;
    int b = blockIdx.y;
    int t = threadIdx.x;  // 256
    __shared__ int s_j;
    __shared__ float s_invm;
    if (t == 0) {
        unsigned long long pk = g_packed[b * NMASK + i];
        unsigned j  = ~(unsigned)pk;
        unsigned ov = (unsigned)(pk >> 32);
        unsigned fb = (ov & 0x80000000u) ? (ov & 0x7fffffffu) : ~ov;
        float val = __uint_as_float(fb);
        float im  = g_invm[b * NMASK + i];
        g_maxc[b * NMASK + i] = val * im;
        g_bn2[b * NMASK + i] = g_n2[b * HW + np[j]];
        s_j = (int)j;
        s_invm = im;
    }
    __syncthreads();
    int jj = s_j;
    float im = s_invm;
    const float* Am = g_Am + (size_t)b * CH * NMASK;
    const float* Bn = g_Bn + (size_t)b * CH * NCTX;
    size_t o = ((size_t)b * NMASK + i) * CH;
#pragma unroll
    for (int c = t; c < CH; c += 256) {
        g_best[o + c] = Bn[(size_t)c * NCTX + jj];
        g_mskn[o + c] = Am[(size_t)c * NMASK + i] * im;
    }
}

// ---------------- K G: dual-chain warp-specialized scan ----------------------
// 4 blocks x 64 threads. warp0 = consumer running TWO batch chains interleaved
// (B's issue fills A's shuffle latency). warp1 = producer, all cp.async.
#define NRING 8
#define NG (NMASK / 4)

struct ScanState { float s1, rnd; };

__device__ __forceinline__ void scan_step2(
    int i, float mxA, float bnA, float mxB, float bnB,
    float* qA, float* qB, ScanState& stA, ScanState& stB,
    const float (*rA)[2][CH], const float (*rB)[2][CH],
    float* GEA, float* GEB, size_t lo)
{
    int s = i & (NRING - 1);
    float mnA[16], bsA[16], mnB[16], bsB[16];
#pragma unroll
    for (int u = 0; u < 4; u++) {
        float4 a = *(const float4*)&rA[s][0][lo + u * 4];
        mnA[u*4+0]=a.x; mnA[u*4+1]=a.y; mnA[u*4+2]=a.z; mnA[u*4+3]=a.w;
        float4 c = *(const float4*)&rA[s][1][lo + u * 4];
        bsA[u*4+0]=c.x; bsA[u*4+1]=c.y; bsA[u*4+2]=c.z; bsA[u*4+3]=c.w;
        float4 d = *(const float4*)&rB[s][0][lo + u * 4];
        mnB[u*4+0]=d.x; mnB[u*4+1]=d.y; mnB[u*4+2]=d.z; mnB[u*4+3]=d.w;
        float4 e = *(const float4*)&rB[s][1][lo + u * 4];
        bsB[u*4+0]=e.x; bsB[u*4+1]=e.y; bsB[u*4+2]=e.z; bsB[u*4+3]=e.w;
    }
    float p2A[8], pcA[8], p2B[8], pcB[8];
#pragma unroll
    for (int e = 0; e < 8; e++) {
        p2A[e] = __fmaf_rn(mnA[e], qA[e], mnA[e + 8] * qA[e + 8]);
        p2B[e] = __fmaf_rn(mnB[e], qB[e], mnB[e + 8] * qB[e + 8]);
        pcA[e] = __fmaf_rn(bsA[e], qA[e], bsA[e + 8] * qA[e + 8]);
        pcB[e] = __fmaf_rn(bsB[e], qB[e], bsB[e + 8] * qB[e + 8]);
    }
#pragma unroll
    for (int w = 4; w; w >>= 1)
#pragma unroll
        for (int e = 0; e < w; e++) {
            p2A[e] += p2A[e + w]; p2B[e] += p2B[e + w];
            pcA[e] += pcA[e + w]; pcB[e] += pcB[e + w];
        }
    float s2A = p2A[0], cA = pcA[0], s2B = p2B[0], cB = pcB[0];
#pragma unroll
    for (int o = 16; o; o >>= 1) {
        s2A += __shfl_xor_sync(0xffffffffu, s2A, o);
        s2B += __shfl_xor_sync(0xffffffffu, s2B, o);
        cA  += __shfl_xor_sync(0xffffffffu, cA,  o);
        cB  += __shfl_xor_sync(0xffffffffu, cB,  o);
    }
    float sA = fmaxf(s2A, 0.f),  sB = fmaxf(s2B, 0.f);
    float dA = sA * stA.rnd,     dB = sB * stB.rnd;
    float TA = dA + mxA + EPSF,  TB = dB + mxB + EPSF;
    float rTA = frcp(TA),        rTB = frcp(TB);
    float w1A = dA * rTA, w2A = mxA * rTA;
    float w1B = dB * rTB, w2B = mxB * rTB;
#pragma unroll
    for (int e = 0; e < 16; e++) {
        qA[e] = __fmaf_rn(w1A, qA[e], w2A * bsA[e]);
        qB[e] = __fmaf_rn(w1B, qB[e], w2B * bsB[e]);
    }
    float* geA = GEA + (size_t)i * CH + lo;
    float* geB = GEB + (size_t)i * CH + lo;
#pragma unroll
    for (int u = 0; u < 4; u++) {
        float4 w;
        w.x = qA[u*4+0]; w.y = qA[u*4+1]; w.z = qA[u*4+2]; w.w = qA[u*4+3];
        *(float4*)(geA + u * 4) = w;
        float4 v;
        v.x = qB[u*4+0]; v.y = qB[u*4+1]; v.z = qB[u*4+2]; v.w = qB[u*4+3];
        *(float4*)(geB + u * 4) = v;
    }
    // shadow tails (off next step's critical path)
    float aaA = w1A * w1A, abA = w1A * w2A, bbA = w2A * w2A;
    float aaB = w1B * w1B, abB = w1B * w2B, bbB = w2B * w2B;
    stA.s1 = __fmaf_rn(aaA, stA.s1, __fmaf_rn(2.f * abA, cA, bbA * bnA));
    stB.s1 = __fmaf_rn(aaB, stB.s1, __fmaf_rn(2.f * abB, cB, bbB * bnB));
    float rsA = (stA.s1 > 0.f) ? frsq(stA.s1) : 0.f;
    float rsB = (stB.s1 > 0.f) ? frsq(stB.s1) : 0.f;
    stA.rnd = frcp(stA.s1 * rsA + EPSF);
    stB.rnd = frcp(stB.s1 * rsB + EPSF);
}

__global__ void __launch_bounds__(64, 1) k_scan() {
    __shared__ __align__(16) float ringA[NRING][2][CH];  // 32KB
    __shared__ __align__(16) float ringB[NRING][2][CH];  // 32KB
    __shared__ int rflag, cdone;

    int bp = blockIdx.x;              // 0..3
    int bA = bp * 2, bB = bp * 2 + 1;
    int warp = threadIdx.x >> 5;
    int lane = threadIdx.x & 31;

    const float* MNA = g_mskn + (size_t)bA * NMASK * CH;
    const float* BSA = g_best + (size_t)bA * NMASK * CH;
    float*       GEA = g_gen  + (size_t)bA * NMASK * CH;
    const float* MXA = g_maxc + bA * NMASK;
    const float* B2A = g_bn2  + bA * NMASK;
    const float* MNB = g_mskn + (size_t)bB * NMASK * CH;
    const float* BSB = g_best + (size_t)bB * NMASK * CH;
    float*       GEB = g_gen  + (size_t)bB * NMASK * CH;
    const float* MXB = g_maxc + bB * NMASK;
    const float* B2B = g_bn2  + bB * NMASK;
    size_t lo = (size_t)lane * 16;

    if (threadIdx.x == 0) { rflag = -1; cdone = -1; }
    __syncthreads();

#define PRE2(i)                                                               \
    do {                                                                      \
        int s_ = (i) & (NRING - 1);                                           \
        const float* pmA = MNA + (size_t)(i) * CH + lo;                       \
        const float* pbA = BSA + (size_t)(i) * CH + lo;                       \
        const float* pmB = MNB + (size_t)(i) * CH + lo;                       \
        const float* pbB = BSB + (size_t)(i) * CH + lo;                       \
        cp16(&ringA[s_][0][lo],      pmA);  cp16(&ringA[s_][0][lo + 4],  pmA + 4);  \
        cp16(&ringA[s_][0][lo + 8],  pmA + 8); cp16(&ringA[s_][0][lo + 12], pmA + 12); \
        cp16(&ringA[s_][1][lo],      pbA);  cp16(&ringA[s_][1][lo + 4],  pbA + 4);  \
        cp16(&ringA[s_][1][lo + 8],  pbA + 8); cp16(&ringA[s_][1][lo + 12], pbA + 12); \
        cp16(&ringB[s_][0][lo],      pmB);  cp16(&ringB[s_][0][lo + 4],  pmB + 4);  \
        cp16(&ringB[s_][0][lo + 8],  pmB + 8); cp16(&ringB[s_][0][lo + 12], pmB + 12); \
        cp16(&ringB[s_][1][lo],      pbB);  cp16(&ringB[s_][1][lo + 4],  pbB + 4);  \
        cp16(&ringB[s_][1][lo + 8],  pbB + 8); cp16(&ringB[s_][1][lo + 12], pbB + 12); \
    } while (0)

    if (warp == 1) {
        // producer: prologue = groups 0,1 (steps 0..7)
#pragma unroll
        for (int g = 0; g < 2; g++) {
#pragma unroll
            for (int k = 0; k < 4; k++) PRE2(4 * g + k);
            asm volatile("cp.async.commit_group;\n");
        }
#pragma unroll 1
        for (int g = 0; g < NG; g++) {
            if (g == NG - 1) asm volatile("cp.async.wait_group 0;\n");
            else             asm volatile("cp.async.wait_group 1;\n");
            __syncwarp();
            if (lane == 0) st_release_s32(&rflag, 4 * g + 3);
            if (g + 2 < NG) {
                // group g+2 reuses group g's slots; wait consumer past group g
                while (ld_acquire_s32(&cdone) < 4 * g + 3) { }
#pragma unroll
                for (int k = 0; k < 4; k++) PRE2(4 * (g + 2) + k);
                asm volatile("cp.async.commit_group;\n");
            }
        }
    } else {
        // consumer
        float qA[16], qB[16];
#pragma unroll
        for (int e = 0; e < 16; e++) { qA[e] = 0.f; qB[e] = 0.f; }
        ScanState stA, stB;
        stA.s1 = 0.f; stA.rnd = frcp(EPSF);
        stB.s1 = 0.f; stB.rnd = frcp(EPSF);
        int ready = -1;
        float4 mxA4 = *(const float4*)MXA, b2A4 = *(const float4*)B2A;
        float4 mxB4 = *(const float4*)MXB, b2B4 = *(const float4*)B2B;

#pragma unroll 1
        for (int g = 0; g < NG; g++) {
            int i0 = g * 4;
            if (ready < i0 + 3) {
                do { ready = ld_acquire_s32(&rflag); } while (ready < i0 + 3);
            }
            float4 mxA4n = mxA4, b2A4n = b2A4, mxB4n = mxB4, b2B4n = b2B4;
            if (g + 1 < NG) {
                mxA4n = *(const float4*)(MXA + i0 + 4);
                b2A4n = *(const float4*)(B2A + i0 + 4);
                mxB4n = *(const float4*)(MXB + i0 + 4);
                b2B4n = *(const float4*)(B2B + i0 + 4);
            }
            scan_step2(i0 + 0, mxA4.x, b2A4.x, mxB4.x, b2B4.x, qA, qB, stA, stB, ringA, ringB, GEA, GEB, lo);
            scan_step2(i0 + 1, mxA4.y, b2A4.y, mxB4.y, b2B4.y, qA, qB, stA, stB, ringA, ringB, GEA, GEB, lo);
            scan_step2(i0 + 2, mxA4.z, b2A4.z, mxB4.z, b2B4.z, qA, qB, stA, stB, ringA, ringB, GEA, GEB, lo);
            scan_step2(i0 + 3, mxA4.w, b2A4.w, mxB4.w, b2B4.w, qA, qB, stA, stB, ringA, ringB, GEA, GEB, lo);
            mxA4 = mxA4n; b2A4 = b2A4n; mxB4 = mxB4n; b2B4 = b2B4n;
            __syncwarp();
            if (lane == 0) st_release_s32(&cdone, i0 + 3);
        }
    }
}

// ---------------- K H: assemble output ---------------------------------------
__global__ void k_out(const float* __restrict__ x, float* __restrict__ out) {
    int idx = blockIdx.x * 256 + threadIdx.x;
    int p = idx & (HW - 1);
    int c = (idx >> 12) & (CH - 1);
    int b = idx >> 21;
    int mi = g_imask[p];
    float v = (mi >= 0) ? g_gen[(((size_t)b * NMASK) + mi) * CH + c] : x[idx];
    out[idx] = v;
}

// ---------------- launch (k_gemm in profiled slot #4) ------------------------
extern "C" void kernel_launch(void* const* d_in, const int* in_sizes, int n_in,
                              void* d_out, int out_size) {
    const float* x  = (const float*)d_in[0];
    const int*   np = (const int*)d_in[2];
    const int*   mp = (const int*)d_in[3];
    float*       out = (float*)d_out;

    k_gather  <<<dim3(CH, BATCH), 1024>>>(x, np, mp);
    k_part    <<<dim3(HW / 256, BATCH, NSPLIT), 256>>>(x);
    k_invall  <<<BATCH * HW / 256, 256>>>();
    k_gemm    <<<dim3(NCTX / BN, NMASK / BM, BATCH), 256>>>(np);
    k_setup   <<<1, 1024>>>(np, mp);
    k_finalize<<<dim3(NMASK, BATCH), 256>>>(np);
    k_scan    <<<BATCH / 2, 64>>>();
    k_out     <<<(BATCH * CH * HW) / 256, 256>>>(x, out);
}

// round 12
// speedup vs baseline: 1.1873x; 1.1873x over previous
#include <cuda_runtime.h>

#define BATCH 8
#define HW    4096
#define CH    512
#define NMASK 1024
#define NCTX  3072
#define EPSF  1e-8f
#define NSPLIT 4

// ---------------- scratch ----------------------------------------------------
__device__ float g_Am[BATCH * CH * NMASK];            // [b][k][i]
__device__ float g_Bn[BATCH * CH * NCTX];             // [b][k][j]
__device__ float g_best[BATCH * NMASK * CH];
__device__ float g_mskn[BATCH * NMASK * CH];
__device__ float g_gen[BATCH * NMASK * CH];
__device__ float g_part[NSPLIT][BATCH * HW];
__device__ float g_maxc[BATCH * NMASK];
__device__ float g_bn2[BATCH * NMASK];
__device__ unsigned long long g_packed[BATCH * NMASK];
__device__ int   g_imask[HW];

// ---------------- helpers ----------------------------------------------------
__device__ __forceinline__ void cp16(void* sdst, const void* gsrc) {
    unsigned saddr = (unsigned)__cvta_generic_to_shared(sdst);
    asm volatile("cp.async.ca.shared.global [%0], [%1], 16;\n" :: "r"(saddr), "l"(gsrc));
}
__device__ __forceinline__ unsigned ford(float f) {
    unsigned u = __float_as_uint(f);
    return (u & 0x80000000u) ? ~u : (u | 0x80000000u);
}
__device__ __forceinline__ float frcp(float x) {
    float r; asm("rcp.approx.f32 %0, %1;" : "=f"(r) : "f"(x)); return r;
}
__device__ __forceinline__ float frsq(float x) {
    float r; asm("rsqrt.approx.f32 %0, %1;" : "=f"(r) : "f"(x)); return r;
}
__device__ __forceinline__ void st_release_s32(volatile int* p, int v) {
    unsigned a = (unsigned)__cvta_generic_to_shared((void*)p);
    asm volatile("st.release.cta.shared.b32 [%0], %1;" :: "r"(a), "r"(v) : "memory");
}
__device__ __forceinline__ int ld_acquire_s32(volatile int* p) {
    unsigned a = (unsigned)__cvta_generic_to_shared((void*)p);
    int v;
    asm volatile("ld.acquire.cta.shared.b32 %0, [%1];" : "=r"(v) : "r"(a) : "memory");
    return v;
}
__device__ __forceinline__ float inv_from_parts(int b, int p) {
    float s = g_part[0][b * HW + p] + g_part[1][b * HW + p]
            + g_part[2][b * HW + p] + g_part[3][b * HW + p];
    return 1.f / (sqrtf(s) + EPSF);
}

// ---------------- K1: prep (gather + partial norms + imask, by block role) --
__global__ void k_prep(const float* __restrict__ x,
                       const int* __restrict__ np, const int* __restrict__ mp) {
    int bx = blockIdx.x;
    int t = threadIdx.x;        // 1024
    if (bx < CH * BATCH) {
        // ---- gather role: block = (k, b) ----
        int k = bx & (CH - 1);
        int b = bx >> 9;
        if (bx == 0) {
#pragma unroll
            for (int i = t; i < BATCH * NMASK; i += 1024) g_packed[i] = 0ull;
        }
        const float* row = x + ((size_t)b * CH + k) * HW;
        g_Am[((size_t)b * CH + k) * NMASK + t] = row[mp[t]];
#pragma unroll
        for (int j = t; j < NCTX; j += 1024)
            g_Bn[((size_t)b * CH + k) * NCTX + j] = row[np[j]];
    } else if (bx < CH * BATCH + BATCH * NSPLIT) {
        // ---- partial-norm role: block = (b, z) ----
        int idx = bx - CH * BATCH;
        int b = idx >> 2, z = idx & 3;
        const float* base = x + ((size_t)b * CH + (size_t)z * (CH / NSPLIT)) * HW;
#pragma unroll 1
        for (int p = t; p < HW; p += 1024) {
            float s = 0.f;
#pragma unroll 8
            for (int c = 0; c < CH / NSPLIT; c++) {
                float v = base[(size_t)c * HW + p];
                s += v * v;
            }
            g_part[z][b * HW + p] = s;
        }
    } else {
        // ---- imask role: single block ----
        for (int p = t; p < HW; p += 1024) g_imask[p] = -1;
        __syncthreads();
        g_imask[mp[t]] = t;
    }
}

// ---------------- K2: fp32 GEMM (3-stage cp.async, 1 sync/tile) -------------
#define BM 128
#define BN 128
#define BK 16
#define NT (CH / BK)

__global__ void __launch_bounds__(256, 2) k_gemm(const int* __restrict__ np) {
    __shared__ __align__(16) float As[3][BK][BM];
    __shared__ __align__(16) float Bs[3][BK][BN];

    int b  = blockIdx.z;
    int i0 = blockIdx.y * BM;
    int j0 = blockIdx.x * BN;
    int tid = threadIdx.x;
    int tx = tid & 15, ty = tid >> 4;
    int cA = tx * 4;

    const float* A  = g_Am + (size_t)b * CH * NMASK + i0;
    const float* Bp = g_Bn + (size_t)b * CH * NCTX  + j0;

    unsigned long long acc[8][4];
#pragma unroll
    for (int r = 0; r < 8; r++)
#pragma unroll
        for (int q = 0; q < 4; q++) acc[r][q] = 0ull;

#define COPY_TILE(t, s_)                                                      \
    do {                                                                      \
        const float* ga = A  + (size_t)((t) * BK + ty) * NMASK + cA;          \
        const float* gb = Bp + (size_t)((t) * BK + ty) * NCTX  + cA;          \
        cp16(&As[s_][ty][cA],      ga);                                       \
        cp16(&As[s_][ty][64 + cA], ga + 64);                                  \
        cp16(&Bs[s_][ty][cA],      gb);                                       \
        cp16(&Bs[s_][ty][64 + cA], gb + 64);                                  \
        asm volatile("cp.async.commit_group;\n");                             \
    } while (0)

    COPY_TILE(0, 0);
    COPY_TILE(1, 1);

#pragma unroll 1
    for (int t = 0; t < NT; t++) {
        if (t < NT - 1) asm volatile("cp.async.wait_group 1;\n");
        else            asm volatile("cp.async.wait_group 0;\n");
        __syncthreads();
        // prefetch t+2 into slot (t+2)%3 == (t-1)%3: its readers finished compute
        // of tile t-1 before reaching this iteration's barrier
        if (t + 2 < NT) { int sp = (t + 2) % 3; COPY_TILE(t + 2, sp); }
        int s = t % 3;
#pragma unroll
        for (int kk = 0; kk < BK; kk++) {
            float4 a0 = *(const float4*)&As[s][kk][ty * 4];
            float4 a1 = *(const float4*)&As[s][kk][64 + ty * 4];
            ulonglong2 bv0 = *(const ulonglong2*)&Bs[s][kk][tx * 4];
            ulonglong2 bv1 = *(const ulonglong2*)&Bs[s][kk][64 + tx * 4];
            float ar[8] = {a0.x, a0.y, a0.z, a0.w, a1.x, a1.y, a1.z, a1.w};
            unsigned long long bq[4] = {bv0.x, bv0.y, bv1.x, bv1.y};
#pragma unroll
            for (int r = 0; r < 8; r++) {
                unsigned long long a2;
                asm("mov.b64 %0, {%1, %1};" : "=l"(a2) : "r"(__float_as_uint(ar[r])));
#pragma unroll
                for (int q = 0; q < 4; q++)
                    asm("fma.rn.f32x2 %0, %1, %2, %0;"
                        : "+l"(acc[r][q]) : "l"(a2), "l"(bq[q]));
            }
        }
    }

    // epilogue: inverse ctx norms computed inline from g_part
    float invc[8];
#pragma unroll
    for (int g = 0; g < 2; g++)
#pragma unroll
        for (int e = 0; e < 4; e++) {
            int jl = j0 + g * 64 + tx * 4 + e;
            invc[g * 4 + e] = inv_from_parts(b, np[jl]);
        }

#pragma unroll
    for (int r = 0; r < 8; r++) {
        int irow = (r < 4) ? (ty * 4 + r) : (64 + ty * 4 + (r - 4));
        unsigned long long bp = 0ull;
#pragma unroll
        for (int q = 0; q < 4; q++) {
            float lo = __uint_as_float((unsigned)acc[r][q]);
            float hi = __uint_as_float((unsigned)(acc[r][q] >> 32));
            float v0 = lo * invc[q * 2];
            float v1 = hi * invc[q * 2 + 1];
            int jg = j0 + ((q >> 1) * 64) + tx * 4 + (q & 1) * 2;
            unsigned long long p0 = ((unsigned long long)ford(v0) << 32) | (unsigned)(~(unsigned)jg);
            unsigned long long p1 = ((unsigned long long)ford(v1) << 32) | (unsigned)(~(unsigned)(jg + 1));
            if (p0 > bp) bp = p0;
            if (p1 > bp) bp = p1;
        }
#pragma unroll
        for (int o = 1; o < 16; o <<= 1) {
            unsigned long long other = __shfl_xor_sync(0xffffffffu, bp, o);
            if (other > bp) bp = other;
        }
        if (tx == 0) atomicMax(&g_packed[b * NMASK + i0 + irow], bp);
    }
}

// ---------------- K3: finalize (pick decode + maxc/bn2 + best/mskn gather) --
__global__ void k_finalize(const int* __restrict__ np, const int* __restrict__ mp) {
    int i = blockIdx.x;
    int b = blockIdx.y;
    int t = threadIdx.x;  // 256
    __shared__ int s_j;
    __shared__ float s_invm;
    if (t == 0) {
        unsigned long long pk = g_packed[b * NMASK + i];
        unsigned j  = ~(unsigned)pk;
        unsigned ov = (unsigned)(pk >> 32);
        unsigned fb = (ov & 0x80000000u) ? (ov & 0x7fffffffu) : ~ov;
        float val = __uint_as_float(fb);
        float im  = inv_from_parts(b, mp[i]);
        g_maxc[b * NMASK + i] = val * im;
        int p = np[j];
        g_bn2[b * NMASK + i] = g_part[0][b * HW + p] + g_part[1][b * HW + p]
                             + g_part[2][b * HW + p] + g_part[3][b * HW + p];
        s_j = (int)j;
        s_invm = im;
    }
    __syncthreads();
    int jj = s_j;
    float im = s_invm;
    const float* Am = g_Am + (size_t)b * CH * NMASK;
    const float* Bn = g_Bn + (size_t)b * CH * NCTX;
    size_t o = ((size_t)b * NMASK + i) * CH;
#pragma unroll
    for (int c = t; c < CH; c += 256) {
        g_best[o + c] = Bn[(size_t)c * NCTX + jj];
        g_mskn[o + c] = Am[(size_t)c * NMASK + i] * im;
    }
}

// ---------------- K4: scan v4 (R10 config, PROFILED SLOT) -------------------
#define NRING 16
#define NG (NMASK / 4)

struct ScanState { float s1, rnd; };

__device__ __forceinline__ void scan_step(
    int i, float mx, float bn2, float* q, ScanState& st,
    const float (*ring)[2][CH], float* GE, size_t lo)
{
    int s = i & (NRING - 1);
    float mn[16], bs[16];
#pragma unroll
    for (int u = 0; u < 4; u++) {
        float4 a = *(const float4*)&ring[s][0][lo + u * 4];
        mn[u*4+0]=a.x; mn[u*4+1]=a.y; mn[u*4+2]=a.z; mn[u*4+3]=a.w;
        float4 c = *(const float4*)&ring[s][1][lo + u * 4];
        bs[u*4+0]=c.x; bs[u*4+1]=c.y; bs[u*4+2]=c.z; bs[u*4+3]=c.w;
    }
    float p2[8], pc[8];
#pragma unroll
    for (int e = 0; e < 8; e++) {
        p2[e] = __fmaf_rn(mn[e], q[e], mn[e + 8] * q[e + 8]);
        pc[e] = __fmaf_rn(bs[e], q[e], bs[e + 8] * q[e + 8]);
    }
#pragma unroll
    for (int w = 4; w; w >>= 1)
#pragma unroll
        for (int e = 0; e < w; e++) { p2[e] += p2[e + w]; pc[e] += pc[e + w]; }
    float s2 = p2[0], c = pc[0];
#pragma unroll
    for (int o = 16; o; o >>= 1) {
        s2 += __shfl_xor_sync(0xffffffffu, s2, o);
        c  += __shfl_xor_sync(0xffffffffu, c,  o);
    }
    float s2p = fmaxf(s2, 0.f);
    float d   = s2p * st.rnd;
    float T   = d + mx + EPSF;
    float rT  = frcp(T);
    float w1 = d * rT, w2 = mx * rT;
#pragma unroll
    for (int e = 0; e < 16; e++) q[e] = __fmaf_rn(w1, q[e], w2 * bs[e]);
    float* ge = GE + (size_t)i * CH + lo;
#pragma unroll
    for (int u = 0; u < 4; u++) {
        float4 w;
        w.x = q[u*4+0]; w.y = q[u*4+1]; w.z = q[u*4+2]; w.w = q[u*4+3];
        *(float4*)(ge + u * 4) = w;
    }
    float aa = w1 * w1, ab = w1 * w2, bb = w2 * w2;
    st.s1 = __fmaf_rn(aa, st.s1, __fmaf_rn(2.f * ab, c, bb * bn2));
    float rs  = (st.s1 > 0.f) ? frsq(st.s1) : 0.f;
    float nrm = st.s1 * rs;
    st.rnd = frcp(nrm + EPSF);
}

__global__ void __launch_bounds__(64, 1) k_scan() {
    __shared__ __align__(16) float ring[NRING][2][CH];   // 64KB
    __shared__ int rflag, cdone;

    int b = blockIdx.x;
    int warp = threadIdx.x >> 5;
    int lane = threadIdx.x & 31;

    const float* MN  = g_mskn + (size_t)b * NMASK * CH;
    const float* BS  = g_best + (size_t)b * NMASK * CH;
    float*       GE  = g_gen  + (size_t)b * NMASK * CH;
    const float* MX  = g_maxc + b * NMASK;
    const float* BN2 = g_bn2  + b * NMASK;
    size_t lo = (size_t)lane * 16;

    if (threadIdx.x == 0) { rflag = -1; cdone = -1; }
    __syncthreads();

#define PRE(i, s)                                                             \
    do {                                                                      \
        const float* pm = MN + (size_t)(i) * CH + lo;                         \
        const float* pb = BS + (size_t)(i) * CH + lo;                         \
        cp16(&ring[s][0][lo],      pm);                                       \
        cp16(&ring[s][0][lo + 4],  pm + 4);                                   \
        cp16(&ring[s][0][lo + 8],  pm + 8);                                   \
        cp16(&ring[s][0][lo + 12], pm + 12);                                  \
        cp16(&ring[s][1][lo],      pb);                                       \
        cp16(&ring[s][1][lo + 4],  pb + 4);                                   \
        cp16(&ring[s][1][lo + 8],  pb + 8);                                   \
        cp16(&ring[s][1][lo + 12], pb + 12);                                  \
    } while (0)

    if (warp == 1) {
        // producer
#pragma unroll
        for (int g = 0; g < 4; g++) {
#pragma unroll
            for (int k = 0; k < 4; k++) PRE(4 * g + k, (4 * g + k) & (NRING - 1));
            asm volatile("cp.async.commit_group;\n");
        }
#pragma unroll 1
        for (int g = 0; g < NG; g++) {
            int rem = NG - 1 - g;
            if (rem >= 3)      asm volatile("cp.async.wait_group 3;\n");
            else if (rem == 2) asm volatile("cp.async.wait_group 2;\n");
            else if (rem == 1) asm volatile("cp.async.wait_group 1;\n");
            else               asm volatile("cp.async.wait_group 0;\n");
            __syncwarp();
            if (lane == 0) st_release_s32(&rflag, 4 * g + 3);
            if (g + 4 < NG) {
                while (ld_acquire_s32(&cdone) < 4 * g + 3) { }
                int s0 = 4 * (g + 4);
#pragma unroll
                for (int k = 0; k < 4; k++) PRE(s0 + k, (s0 + k) & (NRING - 1));
                asm volatile("cp.async.commit_group;\n");
            }
        }
    } else {
        // consumer
        float q[16];
#pragma unroll
        for (int e = 0; e < 16; e++) q[e] = 0.f;
        ScanState st;
        st.s1 = 0.f;
        st.rnd = frcp(EPSF);
        int ready = -1;
        float4 mx4 = *(const float4*)MX;
        float4 b24 = *(const float4*)BN2;

#pragma unroll 1
        for (int g = 0; g < NG; g++) {
            int i0 = g * 4;
            if (ready < i0 + 3) {
                do { ready = ld_acquire_s32(&rflag); } while (ready < i0 + 3);
            }
            float4 mx4n = mx4, b24n = b24;
            if (g + 1 < NG) {
                mx4n = *(const float4*)(MX + i0 + 4);
                b24n = *(const float4*)(BN2 + i0 + 4);
            }
            scan_step(i0 + 0, mx4.x, b24.x, q, st, ring, GE, lo);
            scan_step(i0 + 1, mx4.y, b24.y, q, st, ring, GE, lo);
            scan_step(i0 + 2, mx4.z, b24.z, q, st, ring, GE, lo);
            scan_step(i0 + 3, mx4.w, b24.w, q, st, ring, GE, lo);
            mx4 = mx4n; b24 = b24n;
            __syncwarp();
            if (lane == 0) st_release_s32(&cdone, i0 + 3);
        }
    }
}

// ---------------- K5: assemble output ---------------------------------------
__global__ void k_out(const float* __restrict__ x, float* __restrict__ out) {
    int idx = blockIdx.x * 256 + threadIdx.x;
    int p = idx & (HW - 1);
    int c = (idx >> 12) & (CH - 1);
    int b = idx >> 21;
    int mi = g_imask[p];
    float v = (mi >= 0) ? g_gen[(((size_t)b * NMASK) + mi) * CH + c] : x[idx];
    out[idx] = v;
}

// ---------------- launch (k_scan in profiled slot #4) ------------------------
extern "C" void kernel_launch(void* const* d_in, const int* in_sizes, int n_in,
                              void* d_out, int out_size) {
    const float* x  = (const float*)d_in[0];
    const int*   np = (const int*)d_in[2];
    const int*   mp = (const int*)d_in[3];
    float*       out = (float*)d_out;

    k_prep    <<<CH * BATCH + BATCH * NSPLIT + 1, 1024>>>(x, np, mp);
    k_gemm    <<<dim3(NCTX / BN, NMASK / BM, BATCH), 256>>>(np);
    k_finalize<<<dim3(NMASK, BATCH), 256>>>(np, mp);
    k_scan    <<<BATCH, 64>>>();
    k_out     <<<(BATCH * CH * HW) / 256, 256>>>(x, out);
}

// round 13
// speedup vs baseline: 1.3679x; 1.1522x over previous
#include <cuda_runtime.h>

#define BATCH 8
#define HW    4096
#define CH    512
#define NMASK 1024
#define NCTX  3072
#define EPSF  1e-8f
#define NSPLIT 4

// ---------------- scratch ----------------------------------------------------
__device__ float g_Am[BATCH * CH * NMASK];            // [b][k][i]
__device__ float g_Bn[BATCH * CH * NCTX];             // [b][k][j]
__device__ float g_best[BATCH * NMASK * CH];
__device__ float g_mskn[BATCH * NMASK * CH];
__device__ float g_gen[BATCH * NMASK * CH];
__device__ float g_part[NSPLIT][BATCH * HW];
__device__ float g_invall[BATCH * HW];
__device__ float g_n2[BATCH * HW];
__device__ float g_invc[BATCH * NCTX];
__device__ float g_invm[BATCH * NMASK];
__device__ float g_maxc[BATCH * NMASK];
__device__ float g_bn2[BATCH * NMASK];
__device__ unsigned long long g_packed[BATCH * NMASK];
__device__ int   g_imask[HW];

// ---------------- helpers ----------------------------------------------------
__device__ __forceinline__ void cp16(void* sdst, const void* gsrc) {
    unsigned saddr = (unsigned)__cvta_generic_to_shared(sdst);
    asm volatile("cp.async.ca.shared.global [%0], [%1], 16;\n" :: "r"(saddr), "l"(gsrc));
}
__device__ __forceinline__ unsigned ford(float f) {
    unsigned u = __float_as_uint(f);
    return (u & 0x80000000u) ? ~u : (u | 0x80000000u);
}
__device__ __forceinline__ float frcp(float x) {
    float r; asm("rcp.approx.f32 %0, %1;" : "=f"(r) : "f"(x)); return r;
}
__device__ __forceinline__ float frsq(float x) {
    float r; asm("rsqrt.approx.f32 %0, %1;" : "=f"(r) : "f"(x)); return r;
}
__device__ __forceinline__ void st_release_s32(volatile int* p, int v) {
    unsigned a = (unsigned)__cvta_generic_to_shared((void*)p);
    asm volatile("st.release.cta.shared.b32 [%0], %1;" :: "r"(a), "r"(v) : "memory");
}
__device__ __forceinline__ int ld_acquire_s32(volatile int* p) {
    unsigned a = (unsigned)__cvta_generic_to_shared((void*)p);
    int v;
    asm volatile("ld.acquire.cta.shared.b32 %0, [%1];" : "=r"(v) : "r"(a) : "memory");
    return v;
}

// ---------------- K1a/K1b: column norms -------------------------------------
__global__ void k_part(const float* __restrict__ x) {
    int p = blockIdx.x * 256 + threadIdx.x;
    int b = blockIdx.y;
    int z = blockIdx.z;
    const float* base = x + ((size_t)b * CH + (size_t)z * (CH / NSPLIT)) * HW + p;
    float s = 0.f;
#pragma unroll 8
    for (int c = 0; c < CH / NSPLIT; c++) {
        float v = base[(size_t)c * HW];
        s += v * v;
    }
    g_part[z][b * HW + p] = s;
}
__global__ void k_invall() {
    int i = blockIdx.x * 256 + threadIdx.x;
    float s = g_part[0][i] + g_part[1][i] + g_part[2][i] + g_part[3][i];
    g_n2[i] = s;
    g_invall[i] = 1.f / (sqrtf(s) + EPSF);
}

// ---------------- K2: setup --------------------------------------------------
__global__ void k_setup(const int* __restrict__ np, const int* __restrict__ mp) {
    int t = threadIdx.x;  // 1024, 1 block
    for (int p = t; p < HW; p += 1024) g_imask[p] = -1;
    __syncthreads();
    g_imask[mp[t]] = t;
    for (int i = t; i < BATCH * NMASK; i += 1024) g_packed[i] = 0ull;
    for (int i = t; i < BATCH * NMASK; i += 1024) {
        int b = i / NMASK;
        g_invm[i] = g_invall[b * HW + mp[i % NMASK]];
    }
    for (int j = t; j < BATCH * NCTX; j += 1024) {
        int b = j / NCTX;
        g_invc[j] = g_invall[b * HW + np[j % NCTX]];
    }
}

// ---------------- K3: gather A/B, K-major ------------------------------------
__global__ void k_gather(const float* __restrict__ x,
                         const int* __restrict__ np, const int* __restrict__ mp) {
    int k = blockIdx.x;
    int b = blockIdx.y;
    int t = threadIdx.x;        // 1024
    const float* row = x + ((size_t)b * CH + k) * HW;
    g_Am[((size_t)b * CH + k) * NMASK + t] = row[mp[t]];
#pragma unroll
    for (int j = t; j < NCTX; j += 1024)
        g_Bn[((size_t)b * CH + k) * NCTX + j] = row[np[j]];
}

// ---------------- K4: fp32 GEMM (2-stage cp.async, f32x2 FFMA) --------------
#define BM 128
#define BN 128
#define BK 16
#define NT (CH / BK)

__global__ void __launch_bounds__(256, 2) k_gemm() {
    __shared__ __align__(16) float As[2][BK][BM];
    __shared__ __align__(16) float Bs[2][BK][BN];

    int b  = blockIdx.z;
    int i0 = blockIdx.y * BM;
    int j0 = blockIdx.x * BN;
    int tid = threadIdx.x;
    int tx = tid & 15, ty = tid >> 4;
    int cA = tx * 4;

    const float* A  = g_Am + (size_t)b * CH * NMASK + i0;
    const float* Bp = g_Bn + (size_t)b * CH * NCTX  + j0;

    unsigned long long acc[8][4];
#pragma unroll
    for (int r = 0; r < 8; r++)
#pragma unroll
        for (int q = 0; q < 4; q++) acc[r][q] = 0ull;

#define COPY_TILE(t)                                                          \
    do {                                                                      \
        int s_ = (t) & 1;                                                     \
        const float* ga = A  + (size_t)((t) * BK + ty) * NMASK + cA;          \
        const float* gb = Bp + (size_t)((t) * BK + ty) * NCTX  + cA;          \
        cp16(&As[s_][ty][cA],      ga);                                       \
        cp16(&As[s_][ty][64 + cA], ga + 64);                                  \
        cp16(&Bs[s_][ty][cA],      gb);                                       \
        cp16(&Bs[s_][ty][64 + cA], gb + 64);                                  \
        asm volatile("cp.async.commit_group;\n");                             \
    } while (0)

    COPY_TILE(0);
    COPY_TILE(1);

#pragma unroll 1
    for (int t = 0; t < NT; t++) {
        if (t < NT - 1) asm volatile("cp.async.wait_group 1;\n");
        else            asm volatile("cp.async.wait_group 0;\n");
        __syncthreads();
        int s = t & 1;
#pragma unroll
        for (int kk = 0; kk < BK; kk++) {
            float4 a0 = *(const float4*)&As[s][kk][ty * 4];
            float4 a1 = *(const float4*)&As[s][kk][64 + ty * 4];
            ulonglong2 bv0 = *(const ulonglong2*)&Bs[s][kk][tx * 4];
            ulonglong2 bv1 = *(const ulonglong2*)&Bs[s][kk][64 + tx * 4];
            float ar[8] = {a0.x, a0.y, a0.z, a0.w, a1.x, a1.y, a1.z, a1.w};
            unsigned long long bq[4] = {bv0.x, bv0.y, bv1.x, bv1.y};
#pragma unroll
            for (int r = 0; r < 8; r++) {
                unsigned long long a2;
                asm("mov.b64 %0, {%1, %1};" : "=l"(a2) : "r"(__float_as_uint(ar[r])));
#pragma unroll
                for (int q = 0; q < 4; q++)
                    asm("fma.rn.f32x2 %0, %1, %2, %0;"
                        : "+l"(acc[r][q]) : "l"(a2), "l"(bq[q]));
            }
        }
        __syncthreads();
        if (t + 2 < NT) COPY_TILE(t + 2);
    }

    float invc[8];
#pragma unroll
    for (int g = 0; g < 2; g++)
#pragma unroll
        for (int e = 0; e < 4; e++)
            invc[g * 4 + e] = g_invc[b * NCTX + j0 + g * 64 + tx * 4 + e];

#pragma unroll
    for (int r = 0; r < 8; r++) {
        int irow = (r < 4) ? (ty * 4 + r) : (64 + ty * 4 + (r - 4));
        unsigned long long bp = 0ull;
#pragma unroll
        for (int q = 0; q < 4; q++) {
            float lo = __uint_as_float((unsigned)acc[r][q]);
            float hi = __uint_as_float((unsigned)(acc[r][q] >> 32));
            float v0 = lo * invc[q * 2];
            float v1 = hi * invc[q * 2 + 1];
            int jg = j0 + ((q >> 1) * 64) + tx * 4 + (q & 1) * 2;
            unsigned long long p0 = ((unsigned long long)ford(v0) << 32) | (unsigned)(~(unsigned)jg);
            unsigned long long p1 = ((unsigned long long)ford(v1) << 32) | (unsigned)(~(unsigned)(jg + 1));
            if (p0 > bp) bp = p0;
            if (p1 > bp) bp = p1;
        }
#pragma unroll
        for (int o = 1; o < 16; o <<= 1) {
            unsigned long long other = __shfl_xor_sync(0xffffffffu, bp, o);
            if (other > bp) bp = other;
        }
        if (tx == 0) atomicMax(&g_packed[b * NMASK + i0 + irow], bp);
    }
}

// ---------------- K5: finalize pick + gather + |best|^2 ----------------------
__global__ void k_finalize(const int* __restrict__ np) {
    int i = blockIdx.x;
    int b = blockIdx.y;
    int t = threadIdx.x;  // 256
    __shared__ int s_j;
    __shared__ float s_invm;
    if (t == 0) {
        unsigned long long pk = g_packed[b * NMASK + i];
        unsigned j  = ~(unsigned)pk;
        unsigned ov = (unsigned)(pk >> 32);
        unsigned fb = (ov & 0x80000000u) ? (ov & 0x7fffffffu) : ~ov;
        float val = __uint_as_float(fb);
        float im  = g_invm[b * NMASK + i];
        g_maxc[b * NMASK + i] = val * im;
        g_bn2[b * NMASK + i] = g_n2[b * HW + np[j]];
        s_j = (int)j;
        s_invm = im;
    }
    __syncthreads();
    int jj = s_j;
    float im = s_invm;
    const float* Am = g_Am + (size_t)b * CH * NMASK;
    const float* Bn = g_Bn + (size_t)b * CH * NCTX;
    size_t o = ((size_t)b * NMASK + i) * CH;
#pragma unroll
    for (int c = t; c < CH; c += 256) {
        g_best[o + c] = Bn[(size_t)c * NCTX + jj];
        g_mskn[o + c] = Am[(size_t)c * NMASK + i] * im;
    }
}

// ---------------- K6: scan v5 — conflict-free interleaved ring ---------------
// Layout [stage][mn/bs][chunk u][lane][4]: lane stride 16B -> each 8-lane
// LDS.128 phase hits all 32 banks exactly once (was 16-way conflicted at
// lane stride 64B). cp.async store side identical addresses -> also clean.
#define NRING 16
#define NG (NMASK / 4)

struct ScanState { float s1, rnd; };

__device__ __forceinline__ void scan_step(
    int i, float mx, float bn2, float* q, ScanState& st,
    const float (*ring)[2][CH], float* GE, int lane)
{
    int s = i & (NRING - 1);
    float mn[16], bs[16];
#pragma unroll
    for (int u = 0; u < 4; u++) {
        float4 a = *(const float4*)&ring[s][0][u * 128 + lane * 4];
        mn[u*4+0]=a.x; mn[u*4+1]=a.y; mn[u*4+2]=a.z; mn[u*4+3]=a.w;
        float4 c = *(const float4*)&ring[s][1][u * 128 + lane * 4];
        bs[u*4+0]=c.x; bs[u*4+1]=c.y; bs[u*4+2]=c.z; bs[u*4+3]=c.w;
    }
    float p2[8], pc[8];
#pragma unroll
    for (int e = 0; e < 8; e++) {
        p2[e] = __fmaf_rn(mn[e], q[e], mn[e + 8] * q[e + 8]);
        pc[e] = __fmaf_rn(bs[e], q[e], bs[e + 8] * q[e + 8]);
    }
#pragma unroll
    for (int w = 4; w; w >>= 1)
#pragma unroll
        for (int e = 0; e < w; e++) { p2[e] += p2[e + w]; pc[e] += pc[e + w]; }
    float s2 = p2[0], c = pc[0];
#pragma unroll
    for (int o = 16; o; o >>= 1) {
        s2 += __shfl_xor_sync(0xffffffffu, s2, o);
        c  += __shfl_xor_sync(0xffffffffu, c,  o);
    }
    float s2p = fmaxf(s2, 0.f);
    float d   = s2p * st.rnd;
    float T   = d + mx + EPSF;
    float rT  = frcp(T);
    float w1 = d * rT, w2 = mx * rT;
#pragma unroll
    for (int e = 0; e < 16; e++) q[e] = __fmaf_rn(w1, q[e], w2 * bs[e]);
    float* ge = GE + (size_t)i * CH + lane * 16;
#pragma unroll
    for (int u = 0; u < 4; u++) {
        float4 w;
        w.x = q[u*4+0]; w.y = q[u*4+1]; w.z = q[u*4+2]; w.w = q[u*4+3];
        *(float4*)(ge + u * 4) = w;
    }
    float aa = w1 * w1, ab = w1 * w2, bb = w2 * w2;
    st.s1 = __fmaf_rn(aa, st.s1, __fmaf_rn(2.f * ab, c, bb * bn2));
    float rs  = (st.s1 > 0.f) ? frsq(st.s1) : 0.f;
    float nrm = st.s1 * rs;
    st.rnd = frcp(nrm + EPSF);
}

__global__ void __launch_bounds__(64, 1) k_scan() {
    __shared__ __align__(16) float ring[NRING][2][CH];   // 64KB
    __shared__ int rflag, cdone;

    int b = blockIdx.x;
    int warp = threadIdx.x >> 5;
    int lane = threadIdx.x & 31;

    const float* MN  = g_mskn + (size_t)b * NMASK * CH;
    const float* BS  = g_best + (size_t)b * NMASK * CH;
    float*       GE  = g_gen  + (size_t)b * NMASK * CH;
    const float* MX  = g_maxc + b * NMASK;
    const float* BN2 = g_bn2  + b * NMASK;

    if (threadIdx.x == 0) { rflag = -1; cdone = -1; }
    __syncthreads();

    // producer copies lane's 16 floats (global lane*16 + u*4) to interleaved
    // smem home (u*128 + lane*4): both sides conflict-free.
#define PRE(i, s)                                                             \
    do {                                                                      \
        const float* pm = MN + (size_t)(i) * CH + lane * 16;                  \
        const float* pb = BS + (size_t)(i) * CH + lane * 16;                  \
        cp16(&ring[s][0][0 * 128 + lane * 4], pm);                            \
        cp16(&ring[s][0][1 * 128 + lane * 4], pm + 4);                        \
        cp16(&ring[s][0][2 * 128 + lane * 4], pm + 8);                        \
        cp16(&ring[s][0][3 * 128 + lane * 4], pm + 12);                       \
        cp16(&ring[s][1][0 * 128 + lane * 4], pb);                            \
        cp16(&ring[s][1][1 * 128 + lane * 4], pb + 4);                        \
        cp16(&ring[s][1][2 * 128 + lane * 4], pb + 8);                        \
        cp16(&ring[s][1][3 * 128 + lane * 4], pb + 12);                       \
    } while (0)

    if (warp == 1) {
        // producer
#pragma unroll
        for (int g = 0; g < 4; g++) {
#pragma unroll
            for (int k = 0; k < 4; k++) PRE(4 * g + k, (4 * g + k) & (NRING - 1));
            asm volatile("cp.async.commit_group;\n");
        }
#pragma unroll 1
        for (int g = 0; g < NG; g++) {
            int rem = NG - 1 - g;
            if (rem >= 3)      asm volatile("cp.async.wait_group 3;\n");
            else if (rem == 2) asm volatile("cp.async.wait_group 2;\n");
            else if (rem == 1) asm volatile("cp.async.wait_group 1;\n");
            else               asm volatile("cp.async.wait_group 0;\n");
            __syncwarp();
            if (lane == 0) st_release_s32(&rflag, 4 * g + 3);
            if (g + 4 < NG) {
                while (ld_acquire_s32(&cdone) < 4 * g + 3) { }
                int s0 = 4 * (g + 4);
#pragma unroll
                for (int k = 0; k < 4; k++) PRE(s0 + k, (s0 + k) & (NRING - 1));
                asm volatile("cp.async.commit_group;\n");
            }
        }
    } else {
        // consumer
        float q[16];
#pragma unroll
        for (int e = 0; e < 16; e++) q[e] = 0.f;
        ScanState st;
        st.s1 = 0.f;
        st.rnd = frcp(EPSF);
        int ready = -1;
        float4 mx4 = *(const float4*)MX;
        float4 b24 = *(const float4*)BN2;

#pragma unroll 1
        for (int g = 0; g < NG; g++) {
            int i0 = g * 4;
            if (ready < i0 + 3) {
                do { ready = ld_acquire_s32(&rflag); } while (ready < i0 + 3);
            }
            float4 mx4n = mx4, b24n = b24;
            if (g + 1 < NG) {
                mx4n = *(const float4*)(MX + i0 + 4);
                b24n = *(const float4*)(BN2 + i0 + 4);
            }
            scan_step(i0 + 0, mx4.x, b24.x, q, st, ring, GE, lane);
            scan_step(i0 + 1, mx4.y, b24.y, q, st, ring, GE, lane);
            scan_step(i0 + 2, mx4.z, b24.z, q, st, ring, GE, lane);
            scan_step(i0 + 3, mx4.w, b24.w, q, st, ring, GE, lane);
            mx4 = mx4n; b24 = b24n;
            __syncwarp();
            if (lane == 0) st_release_s32(&cdone, i0 + 3);
        }
    }
}

// ---------------- K7: assemble output ---------------------------------------
__global__ void k_out(const float* __restrict__ x, float* __restrict__ out) {
    int idx = blockIdx.x * 256 + threadIdx.x;
    int p = idx & (HW - 1);
    int c = (idx >> 12) & (CH - 1);
    int b = idx >> 21;
    int mi = g_imask[p];
    float v = (mi >= 0) ? g_gen[(((size_t)b * NMASK) + mi) * CH + c] : x[idx];
    out[idx] = v;
}

// ---------------- launch -----------------------------------------------------
extern "C" void kernel_launch(void* const* d_in, const int* in_sizes, int n_in,
                              void* d_out, int out_size) {
    const float* x  = (const float*)d_in[0];
    const int*   np = (const int*)d_in[2];
    const int*   mp = (const int*)d_in[3];
    float*       out = (float*)d_out;

    k_part    <<<dim3(HW / 256, BATCH, NSPLIT), 256>>>(x);
    k_invall  <<<BATCH * HW / 256, 256>>>();
    k_setup   <<<1, 1024>>>(np, mp);
    k_gather  <<<dim3(CH, BATCH), 1024>>>(x, np, mp);
    k_gemm    <<<dim3(NCTX / BN, NMASK / BM, BATCH), 256>>>();
    k_finalize<<<dim3(NMASK, BATCH), 256>>>(np);
    k_scan    <<<BATCH, 64>>>();
    k_out     <<<(BATCH * CH * HW) / 256, 256>>>(x, out);
}